// round 2
// baseline (speedup 1.0000x reference)
#include <cuda_runtime.h>

#define ND 128
#define MAX_NODES 100000
#define MAX_EDGES 625000
#define TILE_R 64
#define KC 32
#define NT 256

// Scratch for scatter-mean aggregation (allocation-free rule: device globals).
__device__ float g_agg[(size_t)MAX_NODES * ND];
__device__ float g_deg[MAX_NODES];

__global__ void zero_kernel(int n_nodes) {
    int stride = gridDim.x * blockDim.x;
    int total = n_nodes * ND;
    for (int i = blockIdx.x * blockDim.x + threadIdx.x; i < total; i += stride)
        g_agg[i] = 0.0f;
    for (int i = blockIdx.x * blockDim.x + threadIdx.x; i < n_nodes; i += stride)
        g_deg[i] = 0.0f;
}

// ---------------------------------------------------------------------------
// Kernel A: messages = relu([h[src] | e] @ Pw + Pb), atomic scatter-add into
// g_agg[tgt], and degree counting. K = 256.
// Block: 256 threads, computes TILE_R=64 edges x 128 cols.
// Thread micro-tile: 4 rows x 8 cols.  row_t = tid/16, col_t = tid%16.
// ---------------------------------------------------------------------------
__global__ void msg_scatter_kernel(const float* __restrict__ h,
                                   const float* __restrict__ e,
                                   const int* __restrict__ src,
                                   const int* __restrict__ tgt,
                                   const float* __restrict__ Pw,
                                   const float* __restrict__ Pb,
                                   int n_edges) {
    __shared__ float Xs[TILE_R][KC + 1];
    __shared__ float Ws[KC][ND];
    __shared__ int s_src[TILE_R];
    __shared__ int s_tgt[TILE_R];

    const int tid = threadIdx.x;
    const int e0 = blockIdx.x * TILE_R;
    if (tid < TILE_R) {
        int r = e0 + tid;
        s_src[tid] = (r < n_edges) ? src[r] : 0;
        s_tgt[tid] = (r < n_edges) ? tgt[r] : 0;
    }
    __syncthreads();

    const int row_t = tid >> 4;
    const int col_t = tid & 15;

    float acc[4][8];
#pragma unroll
    for (int i = 0; i < 4; i++)
#pragma unroll
        for (int j = 0; j < 8; j++) acc[i][j] = 0.0f;

    for (int kk = 0; kk < 256; kk += KC) {
        // Gather X tile [64][32]: cols 0..127 -> h[src], 128..255 -> e[row]
        for (int t = tid; t < TILE_R * KC; t += NT) {
            int r = t / KC;
            int c = t % KC;
            int gr = e0 + r;
            float v = 0.0f;
            if (gr < n_edges) {
                int k = kk + c;
                if (k < 128) v = h[(size_t)s_src[r] * ND + k];
                else         v = e[(size_t)gr * ND + (k - 128)];
            }
            Xs[r][c] = v;
        }
        // Weight chunk [32][128] via float4
        {
            const float4* Wg = (const float4*)(Pw + (size_t)kk * ND);
            float4* Wsv = (float4*)(&Ws[0][0]);
            for (int t = tid; t < KC * ND / 4; t += NT) Wsv[t] = Wg[t];
        }
        __syncthreads();

#pragma unroll
        for (int k = 0; k < KC; k++) {
            float xv[4], wv[8];
#pragma unroll
            for (int i = 0; i < 4; i++) xv[i] = Xs[row_t * 4 + i][k];
#pragma unroll
            for (int j = 0; j < 8; j++) wv[j] = Ws[k][col_t * 8 + j];
#pragma unroll
            for (int i = 0; i < 4; i++)
#pragma unroll
                for (int j = 0; j < 8; j++) acc[i][j] = fmaf(xv[i], wv[j], acc[i][j]);
        }
        __syncthreads();
    }

    // Epilogue: bias + relu + atomic scatter-add
    float bias[8];
#pragma unroll
    for (int j = 0; j < 8; j++) bias[j] = Pb[col_t * 8 + j];

#pragma unroll
    for (int i = 0; i < 4; i++) {
        int r = row_t * 4 + i;
        int gr = e0 + r;
        if (gr < n_edges) {
            float* aggrow = &g_agg[(size_t)s_tgt[r] * ND + col_t * 8];
#pragma unroll
            for (int j = 0; j < 8; j++) {
                float v = fmaxf(acc[i][j] + bias[j], 0.0f);
                atomicAdd(&aggrow[j], v);
            }
        }
    }
    if (col_t == 0) {
#pragma unroll
        for (int i = 0; i < 4; i++) {
            int r = row_t * 4 + i;
            int gr = e0 + r;
            if (gr < n_edges) atomicAdd(&g_deg[s_tgt[r]], 1.0f);
        }
    }
}

// ---------------------------------------------------------------------------
// Kernel B: e_new = relu([e | h[src] | h[tgt]] @ Ww + Wb).  K = 384.
// ---------------------------------------------------------------------------
__global__ void edge_update_kernel(const float* __restrict__ h,
                                   const float* __restrict__ e,
                                   const int* __restrict__ src,
                                   const int* __restrict__ tgt,
                                   const float* __restrict__ Ww,
                                   const float* __restrict__ Wb,
                                   float* __restrict__ out_e,
                                   int n_edges) {
    __shared__ float Xs[TILE_R][KC + 1];
    __shared__ float Ws[KC][ND];
    __shared__ int s_src[TILE_R];
    __shared__ int s_tgt[TILE_R];

    const int tid = threadIdx.x;
    const int e0 = blockIdx.x * TILE_R;
    if (tid < TILE_R) {
        int r = e0 + tid;
        s_src[tid] = (r < n_edges) ? src[r] : 0;
        s_tgt[tid] = (r < n_edges) ? tgt[r] : 0;
    }
    __syncthreads();

    const int row_t = tid >> 4;
    const int col_t = tid & 15;

    float acc[4][8];
#pragma unroll
    for (int i = 0; i < 4; i++)
#pragma unroll
        for (int j = 0; j < 8; j++) acc[i][j] = 0.0f;

    for (int kk = 0; kk < 384; kk += KC) {
        for (int t = tid; t < TILE_R * KC; t += NT) {
            int r = t / KC;
            int c = t % KC;
            int gr = e0 + r;
            float v = 0.0f;
            if (gr < n_edges) {
                int k = kk + c;
                if (k < 128)      v = e[(size_t)gr * ND + k];
                else if (k < 256) v = h[(size_t)s_src[r] * ND + (k - 128)];
                else              v = h[(size_t)s_tgt[r] * ND + (k - 256)];
            }
            Xs[r][c] = v;
        }
        {
            const float4* Wg = (const float4*)(Ww + (size_t)kk * ND);
            float4* Wsv = (float4*)(&Ws[0][0]);
            for (int t = tid; t < KC * ND / 4; t += NT) Wsv[t] = Wg[t];
        }
        __syncthreads();

#pragma unroll
        for (int k = 0; k < KC; k++) {
            float xv[4], wv[8];
#pragma unroll
            for (int i = 0; i < 4; i++) xv[i] = Xs[row_t * 4 + i][k];
#pragma unroll
            for (int j = 0; j < 8; j++) wv[j] = Ws[k][col_t * 8 + j];
#pragma unroll
            for (int i = 0; i < 4; i++)
#pragma unroll
                for (int j = 0; j < 8; j++) acc[i][j] = fmaf(xv[i], wv[j], acc[i][j]);
        }
        __syncthreads();
    }

    float bias[8];
#pragma unroll
    for (int j = 0; j < 8; j++) bias[j] = Wb[col_t * 8 + j];

#pragma unroll
    for (int i = 0; i < 4; i++) {
        int gr = e0 + row_t * 4 + i;
        if (gr < n_edges) {
            float4 v0, v1;
            v0.x = fmaxf(acc[i][0] + bias[0], 0.0f);
            v0.y = fmaxf(acc[i][1] + bias[1], 0.0f);
            v0.z = fmaxf(acc[i][2] + bias[2], 0.0f);
            v0.w = fmaxf(acc[i][3] + bias[3], 0.0f);
            v1.x = fmaxf(acc[i][4] + bias[4], 0.0f);
            v1.y = fmaxf(acc[i][5] + bias[5], 0.0f);
            v1.z = fmaxf(acc[i][6] + bias[6], 0.0f);
            v1.w = fmaxf(acc[i][7] + bias[7], 0.0f);
            float4* o = (float4*)&out_e[(size_t)gr * ND + col_t * 8];
            o[0] = v0;
            o[1] = v1;
        }
    }
}

// ---------------------------------------------------------------------------
// Kernel C: h_new = relu([h | agg/max(deg,1)] @ Qw + Qb).  K = 256.
// ---------------------------------------------------------------------------
__global__ void node_update_kernel(const float* __restrict__ h,
                                   const float* __restrict__ Qw,
                                   const float* __restrict__ Qb,
                                   float* __restrict__ out_h,
                                   int n_nodes) {
    __shared__ float Xs[TILE_R][KC + 1];
    __shared__ float Ws[KC][ND];
    __shared__ float s_inv[TILE_R];

    const int tid = threadIdx.x;
    const int r0 = blockIdx.x * TILE_R;
    if (tid < TILE_R) {
        int r = r0 + tid;
        float inv = 0.0f;
        if (r < n_nodes) inv = 1.0f / fmaxf(g_deg[r], 1.0f);
        s_inv[tid] = inv;
    }
    __syncthreads();

    const int row_t = tid >> 4;
    const int col_t = tid & 15;

    float acc[4][8];
#pragma unroll
    for (int i = 0; i < 4; i++)
#pragma unroll
        for (int j = 0; j < 8; j++) acc[i][j] = 0.0f;

    for (int kk = 0; kk < 256; kk += KC) {
        for (int t = tid; t < TILE_R * KC; t += NT) {
            int r = t / KC;
            int c = t % KC;
            int gr = r0 + r;
            float v = 0.0f;
            if (gr < n_nodes) {
                int k = kk + c;
                if (k < 128) v = h[(size_t)gr * ND + k];
                else         v = g_agg[(size_t)gr * ND + (k - 128)] * s_inv[r];
            }
            Xs[r][c] = v;
        }
        {
            const float4* Wg = (const float4*)(Qw + (size_t)kk * ND);
            float4* Wsv = (float4*)(&Ws[0][0]);
            for (int t = tid; t < KC * ND / 4; t += NT) Wsv[t] = Wg[t];
        }
        __syncthreads();

#pragma unroll
        for (int k = 0; k < KC; k++) {
            float xv[4], wv[8];
#pragma unroll
            for (int i = 0; i < 4; i++) xv[i] = Xs[row_t * 4 + i][k];
#pragma unroll
            for (int j = 0; j < 8; j++) wv[j] = Ws[k][col_t * 8 + j];
#pragma unroll
            for (int i = 0; i < 4; i++)
#pragma unroll
                for (int j = 0; j < 8; j++) acc[i][j] = fmaf(xv[i], wv[j], acc[i][j]);
        }
        __syncthreads();
    }

    float bias[8];
#pragma unroll
    for (int j = 0; j < 8; j++) bias[j] = Qb[col_t * 8 + j];

#pragma unroll
    for (int i = 0; i < 4; i++) {
        int gr = r0 + row_t * 4 + i;
        if (gr < n_nodes) {
            float4 v0, v1;
            v0.x = fmaxf(acc[i][0] + bias[0], 0.0f);
            v0.y = fmaxf(acc[i][1] + bias[1], 0.0f);
            v0.z = fmaxf(acc[i][2] + bias[2], 0.0f);
            v0.w = fmaxf(acc[i][3] + bias[3], 0.0f);
            v1.x = fmaxf(acc[i][4] + bias[4], 0.0f);
            v1.y = fmaxf(acc[i][5] + bias[5], 0.0f);
            v1.z = fmaxf(acc[i][6] + bias[6], 0.0f);
            v1.w = fmaxf(acc[i][7] + bias[7], 0.0f);
            float4* o = (float4*)&out_h[(size_t)gr * ND + col_t * 8];
            o[0] = v0;
            o[1] = v1;
        }
    }
}

extern "C" void kernel_launch(void* const* d_in, const int* in_sizes, int n_in,
                              void* d_out, int out_size) {
    // Inputs per metadata order: h, e, edge_index, P_w, P_b, Q_w, Q_b, W_w, W_b
    // edge_index: JAX x64 is disabled by default -> int32 on device.
    const float* h   = (const float*)d_in[0];
    const float* e   = (const float*)d_in[1];
    const int*   idx = (const int*)d_in[2];
    const float* Pw  = (const float*)d_in[3];
    const float* Pb  = (const float*)d_in[4];
    const float* Qw  = (const float*)d_in[5];
    const float* Qb  = (const float*)d_in[6];
    const float* Ww  = (const float*)d_in[7];
    const float* Wb  = (const float*)d_in[8];

    int n_nodes = in_sizes[0] / ND;
    int n_edges = in_sizes[1] / ND;
    const int* src = idx;
    const int* tgt = idx + n_edges;

    float* out_h = (float*)d_out;
    float* out_e = out_h + (size_t)n_nodes * ND;

    zero_kernel<<<512, 256>>>(n_nodes);

    int eb = (n_edges + TILE_R - 1) / TILE_R;
    msg_scatter_kernel<<<eb, NT>>>(h, e, src, tgt, Pw, Pb, n_edges);
    edge_update_kernel<<<eb, NT>>>(h, e, src, tgt, Ww, Wb, out_e, n_edges);

    int nb = (n_nodes + TILE_R - 1) / TILE_R;
    node_update_kernel<<<nb, NT>>>(h, Qw, Qb, out_h, n_nodes);
}

// round 5
// speedup vs baseline: 1.1331x; 1.1331x over previous
#include <cuda_runtime.h>
#include <cstdint>

#define ND 128
#define MAX_NODES 100000
#define MAX_EDGES 625000
#define TM 128
#define KCH 32
#define NTHREADS 256

// ---------------- device scratch (allocation-free rule) ---------------------
__device__ float g_agg[(size_t)MAX_NODES * ND];
__device__ float g_deg[MAX_NODES];
// tf32-rounded weight images, same [K][128] row-major layout as the inputs.
__device__ float g_Pimg[256 * ND];
__device__ float g_Qimg[256 * ND];
__device__ float g_Wimg[384 * ND];

__device__ __forceinline__ uint32_t tf32_bits(float x) {
    uint32_t r;
    asm("cvt.rna.tf32.f32 %0, %1;" : "=r"(r) : "f"(x));
    return r;
}
__device__ __forceinline__ float tf32f(float x) { return __uint_as_float(tf32_bits(x)); }

// m16n8k8 tf32 MMA (baseline PTX, works on plain sm_103 target).
// a0=A[g][tg] a1=A[g+8][tg] a2=A[g][tg+4] a3=A[g+8][tg+4]
// b0=B[tg][g] b1=B[tg+4][g]   (B is k x n)
// c0=C[g][2tg] c1=C[g][2tg+1] c2=C[g+8][2tg] c3=C[g+8][2tg+1]
__device__ __forceinline__ void mma_tf32(float* c, const uint32_t* a, const uint32_t* b) {
    asm volatile(
        "mma.sync.aligned.m16n8k8.row.col.f32.tf32.tf32.f32 "
        "{%0,%1,%2,%3}, {%4,%5,%6,%7}, {%8,%9}, {%0,%1,%2,%3};"
        : "+f"(c[0]), "+f"(c[1]), "+f"(c[2]), "+f"(c[3])
        : "r"(a[0]), "r"(a[1]), "r"(a[2]), "r"(a[3]), "r"(b[0]), "r"(b[1]));
}

__device__ __forceinline__ void red_add_v2(float* ptr, float v0, float v1) {
    asm volatile("red.global.add.v2.f32 [%0], {%1,%2};"
                 :: "l"(ptr), "f"(v0), "f"(v1) : "memory");
}

// ---------------- prep: zero agg/deg, tf32-round weights --------------------
__global__ void prep_kernel(const float* __restrict__ Pw, const float* __restrict__ Qw,
                            const float* __restrict__ Ww, int n_nodes) {
    int stride = gridDim.x * blockDim.x;
    int t0 = blockIdx.x * blockDim.x + threadIdx.x;
    for (int i = t0; i < n_nodes * ND; i += stride) g_agg[i] = 0.0f;
    for (int i = t0; i < n_nodes; i += stride) g_deg[i] = 0.0f;
    for (int i = t0; i < 256 * ND; i += stride) {
        g_Pimg[i] = tf32f(Pw[i]);
        g_Qimg[i] = tf32f(Qw[i]);
    }
    for (int i = t0; i < 384 * ND; i += stride) g_Wimg[i] = tf32f(Ww[i]);
}

// ---------------- fused gather-GEMM-epilogue kernel -------------------------
// MODE 0: msg    X=[h[src]|e]        K=256  epi: relu+bias -> red.v2 agg + deg
// MODE 1: edge   X=[e|h[src]|h[tgt]] K=384  epi: relu+bias -> out
// MODE 2: node   X=[h|agg*inv]       K=256  epi: relu+bias -> out
template <int KTOT, int MODE>
__global__ __launch_bounds__(NTHREADS)
void gemm_kernel(const float* __restrict__ h, const float* __restrict__ e,
                 const int* __restrict__ src, const int* __restrict__ tgt,
                 const float* __restrict__ bias, float* __restrict__ out,
                 int n_rows) {
    // Xs stride 36: bank = (r*36+c)%32 = (4r+c)%32 -> conflict-free frag loads.
    // Ws stride 136: bank = (k*136+n)%32 = (8k+n)%32 -> conflict-free.
    __shared__ float Xs[TM][36];
    __shared__ float Ws[KCH][136];
    __shared__ int s_src[TM];
    __shared__ int s_tgt[TM];
    __shared__ float s_inv[TM];
    __shared__ float s_bias[ND];

    const int tid = threadIdx.x;
    const int wid = tid >> 5;
    const int lane = tid & 31;
    const int r0 = blockIdx.x * TM;

    if (tid < TM) {
        int r = r0 + tid;
        bool ok = r < n_rows;
        if (MODE == 0 || MODE == 1) {
            s_src[tid] = ok ? src[r] : 0;
            s_tgt[tid] = ok ? tgt[r] : 0;
        }
        if (MODE == 2) s_inv[tid] = ok ? (1.0f / fmaxf(g_deg[r], 1.0f)) : 0.0f;
    }
    if (tid < ND) s_bias[tid] = bias[tid];
    __syncthreads();

    const float* Wimg = (MODE == 0) ? g_Pimg : (MODE == 1) ? g_Wimg : g_Qimg;

    // warp tile: wm in [0,4) rows of 32, wn in [0,2) cols of 64
    const int wm = wid >> 1;
    const int wn = wid & 1;
    const int m_base = wm * 32;
    const int n_base = wn * 64;
    const int g = lane >> 2;   // groupID
    const int tg = lane & 3;   // threadID_in_group

    float c[2][8][4];
#pragma unroll
    for (int i = 0; i < 2; i++)
#pragma unroll
        for (int j = 0; j < 8; j++)
#pragma unroll
            for (int t = 0; t < 4; t++) c[i][j][t] = 0.0f;

    const int NCH = KTOT / KCH;
    for (int q = 0; q < NCH; q++) {
        const int kk = q * KCH;
        // ---- gather X chunk [128][32]: one warp per row slice, coalesced ----
        for (int i = tid; i < TM * KCH; i += NTHREADS) {
            int r = i >> 5;
            int cc = i & 31;
            int gr = r0 + r;
            float v = 0.0f;
            if (gr < n_rows) {
                int k = kk + cc;
                if (MODE == 0) {
                    v = (k < 128) ? h[(size_t)s_src[r] * ND + k]
                                  : e[(size_t)gr * ND + (k - 128)];
                } else if (MODE == 1) {
                    if (k < 128)      v = e[(size_t)gr * ND + k];
                    else if (k < 256) v = h[(size_t)s_src[r] * ND + (k - 128)];
                    else              v = h[(size_t)s_tgt[r] * ND + (k - 256)];
                } else {
                    v = (k < 128) ? h[(size_t)gr * ND + k]
                                  : g_agg[(size_t)gr * ND + (k - 128)] * s_inv[r];
                }
            }
            Xs[r][cc] = tf32f(v);
        }
        // ---- weight chunk [32][128] from tf32 image (L2-hot) ----
        for (int i = tid; i < KCH * ND; i += NTHREADS) {
            int k = i >> 7;
            int n = i & 127;
            Ws[k][n] = Wimg[(size_t)(kk + k) * ND + n];
        }
        __syncthreads();

        // ---- 4 k-steps of m16n8k8 ----
#pragma unroll
        for (int ks = 0; ks < 4; ks++) {
            const int k0 = ks * 8;
            uint32_t a[2][4];
#pragma unroll
            for (int mat = 0; mat < 2; mat++) {
                int mr = m_base + mat * 16;
                a[mat][0] = __float_as_uint(Xs[mr + g][k0 + tg]);
                a[mat][1] = __float_as_uint(Xs[mr + g + 8][k0 + tg]);
                a[mat][2] = __float_as_uint(Xs[mr + g][k0 + tg + 4]);
                a[mat][3] = __float_as_uint(Xs[mr + g + 8][k0 + tg + 4]);
            }
            uint32_t b[8][2];
#pragma unroll
            for (int nat = 0; nat < 8; nat++) {
                b[nat][0] = __float_as_uint(Ws[k0 + tg][n_base + nat * 8 + g]);
                b[nat][1] = __float_as_uint(Ws[k0 + tg + 4][n_base + nat * 8 + g]);
            }
#pragma unroll
            for (int mat = 0; mat < 2; mat++)
#pragma unroll
                for (int nat = 0; nat < 8; nat++)
                    mma_tf32(c[mat][nat], a[mat], b[nat]);
        }
        __syncthreads();
    }

    // ---- epilogue (registers only; no sync needed) ----
#pragma unroll
    for (int mat = 0; mat < 2; mat++) {
        int row0 = m_base + mat * 16 + g;
        int row1 = row0 + 8;
        int gr0 = r0 + row0;
        int gr1 = r0 + row1;
#pragma unroll
        for (int nat = 0; nat < 8; nat++) {
            int col = n_base + nat * 8 + tg * 2;
            float b0 = s_bias[col], b1 = s_bias[col + 1];
            float v00 = fmaxf(c[mat][nat][0] + b0, 0.0f);
            float v01 = fmaxf(c[mat][nat][1] + b1, 0.0f);
            float v10 = fmaxf(c[mat][nat][2] + b0, 0.0f);
            float v11 = fmaxf(c[mat][nat][3] + b1, 0.0f);
            if (MODE == 0) {
                if (gr0 < n_rows)
                    red_add_v2(&g_agg[(size_t)s_tgt[row0] * ND + col], v00, v01);
                if (gr1 < n_rows)
                    red_add_v2(&g_agg[(size_t)s_tgt[row1] * ND + col], v10, v11);
            } else {
                if (gr0 < n_rows) {
                    float2* p = (float2*)&out[(size_t)gr0 * ND + col];
                    *p = make_float2(v00, v01);
                }
                if (gr1 < n_rows) {
                    float2* p = (float2*)&out[(size_t)gr1 * ND + col];
                    *p = make_float2(v10, v11);
                }
            }
        }
        if (MODE == 0 && wn == 0 && tg == 0) {
            if (gr0 < n_rows) atomicAdd(&g_deg[s_tgt[row0]], 1.0f);
            if (gr1 < n_rows) atomicAdd(&g_deg[s_tgt[row1]], 1.0f);
        }
    }
}

// ---------------- launch ----------------------------------------------------
extern "C" void kernel_launch(void* const* d_in, const int* in_sizes, int n_in,
                              void* d_out, int out_size) {
    // metadata order: h, e, edge_index(int32), P_w, P_b, Q_w, Q_b, W_w, W_b
    const float* h   = (const float*)d_in[0];
    const float* e   = (const float*)d_in[1];
    const int*   idx = (const int*)d_in[2];
    const float* Pw  = (const float*)d_in[3];
    const float* Pb  = (const float*)d_in[4];
    const float* Qw  = (const float*)d_in[5];
    const float* Qb  = (const float*)d_in[6];
    const float* Ww  = (const float*)d_in[7];
    const float* Wb  = (const float*)d_in[8];

    int n_nodes = in_sizes[0] / ND;
    int n_edges = in_sizes[1] / ND;
    const int* src = idx;
    const int* tgt = idx + n_edges;

    float* out_h = (float*)d_out;
    float* out_e = out_h + (size_t)n_nodes * ND;

    prep_kernel<<<256, 256>>>(Pw, Qw, Ww, n_nodes);

    int eb = (n_edges + TM - 1) / TM;
    int nb = (n_nodes + TM - 1) / TM;
    gemm_kernel<256, 0><<<eb, NTHREADS>>>(h, e, src, tgt, Pb, nullptr, n_edges);
    gemm_kernel<384, 1><<<eb, NTHREADS>>>(h, e, src, tgt, Wb, out_e, n_edges);
    gemm_kernel<256, 2><<<nb, NTHREADS>>>(h, e, src, tgt, Qb, out_h, n_nodes);
}

// round 6
// speedup vs baseline: 3.9539x; 3.4895x over previous
#include <cuda_runtime.h>
#include <cstdint>

#define ND 128
#define MAX_NODES 100000
#define MAX_EDGES 625000
#define TM 128
#define KCH 32
#define NTHREADS 256

// ---------------- device scratch (allocation-free rule) ---------------------
__device__ float g_agg[(size_t)MAX_NODES * ND];
__device__ float g_deg[MAX_NODES];
// Fragment-ordered tf32 weight images. Layout: for k-step ks (K/8 steps),
// warp-half wn (n 0..63 / 64..127), lane (0..31): 16 consecutive floats
// = b[nat 0..7][pair 0..1] with n = wn*64+nat*8+(lane>>2),
//   k = ks*8+(lane&3)+pair*4.
__device__ float g_Pfrag[(256 / 8) * 2 * 32 * 16];
__device__ float g_Qfrag[(256 / 8) * 2 * 32 * 16];
__device__ float g_Wfrag[(384 / 8) * 2 * 32 * 16];

__device__ __forceinline__ uint32_t tf32_bits(float x) {
    uint32_t r;
    asm("cvt.rna.tf32.f32 %0, %1;" : "=r"(r) : "f"(x));
    return r;
}
__device__ __forceinline__ float tf32f(float x) { return __uint_as_float(tf32_bits(x)); }

__device__ __forceinline__ uint32_t smem_u32(const void* p) {
    uint32_t a;
    asm("{ .reg .u64 t; cvta.to.shared.u64 t, %1; cvt.u32.u64 %0, t; }"
        : "=r"(a) : "l"(p));
    return a;
}
__device__ __forceinline__ void cp_async16(uint32_t dst, const void* src) {
    asm volatile("cp.async.ca.shared.global [%0], [%1], 16;"
                 :: "r"(dst), "l"(src) : "memory");
}
#define CP_COMMIT() asm volatile("cp.async.commit_group;" ::: "memory")
#define CP_WAIT0()  asm volatile("cp.async.wait_group 0;" ::: "memory")

// m16n8k8 tf32 MMA. Fragment mapping validated in R4/R5 (rel_err 2.9e-4).
__device__ __forceinline__ void mma_tf32(float* c, const uint32_t* a, const uint32_t* b) {
    asm volatile(
        "mma.sync.aligned.m16n8k8.row.col.f32.tf32.tf32.f32 "
        "{%0,%1,%2,%3}, {%4,%5,%6,%7}, {%8,%9}, {%0,%1,%2,%3};"
        : "+f"(c[0]), "+f"(c[1]), "+f"(c[2]), "+f"(c[3])
        : "r"(a[0]), "r"(a[1]), "r"(a[2]), "r"(a[3]), "r"(b[0]), "r"(b[1]));
}
__device__ __forceinline__ void red_add_v2(float* ptr, float v0, float v1) {
    asm volatile("red.global.add.v2.f32 [%0], {%1,%2};"
                 :: "l"(ptr), "f"(v0), "f"(v1) : "memory");
}

// ---------------- prep: zero agg/deg, build fragment-ordered weights --------
__global__ void prep_kernel(const float* __restrict__ Pw, const float* __restrict__ Qw,
                            const float* __restrict__ Ww, int n_nodes) {
    int stride = gridDim.x * blockDim.x;
    int t0 = blockIdx.x * blockDim.x + threadIdx.x;
    for (int i = t0; i < n_nodes * ND; i += stride) g_agg[i] = 0.0f;
    for (int i = t0; i < n_nodes; i += stride) g_deg[i] = 0.0f;
    // decompose frag index: i = ((ks*2 + wn)*32 + lane)*16 + t
    for (int i = t0; i < (256 / 8) * 2 * 32 * 16; i += stride) {
        int t = i & 15, lane = (i >> 4) & 31, wn = (i >> 9) & 1, ks = i >> 10;
        int n = wn * 64 + (t >> 1) * 8 + (lane >> 2);
        int k = ks * 8 + (lane & 3) + (t & 1) * 4;
        g_Pfrag[i] = tf32f(Pw[k * ND + n]);
        g_Qfrag[i] = tf32f(Qw[k * ND + n]);
    }
    for (int i = t0; i < (384 / 8) * 2 * 32 * 16; i += stride) {
        int t = i & 15, lane = (i >> 4) & 31, wn = (i >> 9) & 1, ks = i >> 10;
        int n = wn * 64 + (t >> 1) * 8 + (lane >> 2);
        int k = ks * 8 + (lane & 3) + (t & 1) * 4;
        g_Wfrag[i] = tf32f(Ww[k * ND + n]);
    }
}

// ---------------- fused gather-GEMM-epilogue kernel -------------------------
// MODE 0: msg    X=[h[src]|e]        K=256  epi: relu+bias -> red.v2 agg + deg
// MODE 1: edge   X=[e|h[src]|h[tgt]] K=384  epi: relu+bias -> out
// MODE 2: node   X=[h|agg*inv]       K=256  epi: relu+bias -> out
template <int KTOT, int MODE>
__global__ __launch_bounds__(NTHREADS, 2)
void gemm_kernel(const float* __restrict__ h, const float* __restrict__ e,
                 const int* __restrict__ src, const int* __restrict__ tgt,
                 const float* __restrict__ bias, float* __restrict__ out,
                 int n_rows) {
    // Xs stride 36: fragment-load bank = (4*row + col) % 32 -> conflict-free.
    __shared__ float Xs[2][TM][36];
    __shared__ int s_src[TM];
    __shared__ int s_tgt[TM];
    __shared__ float s_inv[TM];
    __shared__ float s_bias[ND];

    const int tid = threadIdx.x;
    const int wid = tid >> 5;
    const int lane = tid & 31;
    const int r0 = blockIdx.x * TM;

    if (tid < TM) {
        int r = r0 + tid;
        bool ok = r < n_rows;
        if (MODE == 0 || MODE == 1) {
            s_src[tid] = ok ? src[r] : 0;
            s_tgt[tid] = ok ? tgt[r] : 0;
        }
        if (MODE == 2) s_inv[tid] = ok ? (1.0f / fmaxf(g_deg[r], 1.0f)) : 0.0f;
    }
    if (tid < ND) s_bias[tid] = bias[tid];
    __syncthreads();

    const float* Wfrag = (MODE == 0) ? g_Pfrag : (MODE == 1) ? g_Wfrag : g_Qfrag;
    const uint32_t xs_base = smem_u32(Xs);

    const int wm = wid >> 1;          // 4 row-groups of 32
    const int wn = wid & 1;           // 2 col-halves of 64
    const int m_base = wm * 32;
    const int n_base = wn * 64;
    const int g = lane >> 2;
    const int tg = lane & 3;

    float c[2][8][4];
#pragma unroll
    for (int i = 0; i < 2; i++)
#pragma unroll
        for (int j = 0; j < 8; j++)
#pragma unroll
            for (int t = 0; t < 4; t++) c[i][j][t] = 0.0f;

    // rows this thread's A fragments touch (for MODE 2 scaling)
    const int ar[4] = {m_base + g, m_base + g + 8, m_base + 16 + g, m_base + 24 + g};

    // ---- cp.async gather of one K-chunk into buffer b ----
    auto issue_chunk = [&](int q, int b) {
        const int kk = q * KCH;
        for (int i = tid; i < TM * 8; i += NTHREADS) {
            int r = i >> 3;          // row
            int s = i & 7;           // 16B segment
            int gr = r0 + r;
            int grc = (gr < n_rows) ? gr : 0;
            int k = kk + s * 4;
            const float* p;
            if (MODE == 0) {
                p = (k < 128) ? h + (size_t)s_src[r] * ND + k
                              : e + (size_t)grc * ND + (k - 128);
            } else if (MODE == 1) {
                if (k < 128)      p = e + (size_t)grc * ND + k;
                else if (k < 256) p = h + (size_t)s_src[r] * ND + (k - 128);
                else              p = h + (size_t)s_tgt[r] * ND + (k - 256);
            } else {
                p = (k < 128) ? h + (size_t)grc * ND + k
                              : g_agg + (size_t)grc * ND + (k - 128);
            }
            cp_async16(xs_base + (((b * TM) + r) * 36 + s * 4) * 4, p);
        }
        CP_COMMIT();
    };

    const int NCH = KTOT / KCH;
    issue_chunk(0, 0);

    for (int q = 0; q < NCH; q++) {
        const int b = q & 1;
        const int kk = q * KCH;
        CP_WAIT0();
        __syncthreads();
        if (q + 1 < NCH) issue_chunk(q + 1, (q + 1) & 1);

        // scaling factors for this chunk (MODE 2, agg half only)
        float sA[4] = {1.0f, 1.0f, 1.0f, 1.0f};
        if (MODE == 2 && kk >= 128) {
#pragma unroll
            for (int i = 0; i < 4; i++) sA[i] = s_inv[ar[i]];
        }

#pragma unroll
        for (int ks = 0; ks < 4; ks++) {
            const int k0 = ks * 8;
            // A fragments: LDS + scale + tf32 round
            uint32_t a[2][4];
#pragma unroll
            for (int mat = 0; mat < 2; mat++) {
                float f0 = Xs[b][ar[mat * 2]][k0 + tg]         * sA[mat * 2];
                float f1 = Xs[b][ar[mat * 2 + 1]][k0 + tg]     * sA[mat * 2 + 1];
                float f2 = Xs[b][ar[mat * 2]][k0 + tg + 4]     * sA[mat * 2];
                float f3 = Xs[b][ar[mat * 2 + 1]][k0 + tg + 4] * sA[mat * 2 + 1];
                a[mat][0] = tf32_bits(f0);
                a[mat][1] = tf32_bits(f1);
                a[mat][2] = tf32_bits(f2);
                a[mat][3] = tf32_bits(f3);
            }
            // B fragments: 4 coalesced float4 from fragment image (L2-hot)
            const int ks_glob = q * 4 + ks;
            const float4* bp = (const float4*)(Wfrag +
                ((size_t)((ks_glob * 2 + wn) * 32 + lane)) * 16);
            float4 bf0 = __ldg(bp + 0);
            float4 bf1 = __ldg(bp + 1);
            float4 bf2 = __ldg(bp + 2);
            float4 bf3 = __ldg(bp + 3);
            uint32_t bb[8][2];
            bb[0][0] = __float_as_uint(bf0.x); bb[0][1] = __float_as_uint(bf0.y);
            bb[1][0] = __float_as_uint(bf0.z); bb[1][1] = __float_as_uint(bf0.w);
            bb[2][0] = __float_as_uint(bf1.x); bb[2][1] = __float_as_uint(bf1.y);
            bb[3][0] = __float_as_uint(bf1.z); bb[3][1] = __float_as_uint(bf1.w);
            bb[4][0] = __float_as_uint(bf2.x); bb[4][1] = __float_as_uint(bf2.y);
            bb[5][0] = __float_as_uint(bf2.z); bb[5][1] = __float_as_uint(bf2.w);
            bb[6][0] = __float_as_uint(bf3.x); bb[6][1] = __float_as_uint(bf3.y);
            bb[7][0] = __float_as_uint(bf3.z); bb[7][1] = __float_as_uint(bf3.w);
#pragma unroll
            for (int mat = 0; mat < 2; mat++)
#pragma unroll
                for (int nat = 0; nat < 8; nat++)
                    mma_tf32(c[mat][nat], a[mat], bb[nat]);
        }
        __syncthreads();
    }

    // ---- epilogue ----
#pragma unroll
    for (int mat = 0; mat < 2; mat++) {
        int row0 = m_base + mat * 16 + g;
        int row1 = row0 + 8;
        int gr0 = r0 + row0;
        int gr1 = r0 + row1;
#pragma unroll
        for (int nat = 0; nat < 8; nat++) {
            int col = n_base + nat * 8 + tg * 2;
            float b0 = s_bias[col], b1 = s_bias[col + 1];
            float v00 = fmaxf(c[mat][nat][0] + b0, 0.0f);
            float v01 = fmaxf(c[mat][nat][1] + b1, 0.0f);
            float v10 = fmaxf(c[mat][nat][2] + b0, 0.0f);
            float v11 = fmaxf(c[mat][nat][3] + b1, 0.0f);
            if (MODE == 0) {
                if (gr0 < n_rows)
                    red_add_v2(&g_agg[(size_t)s_tgt[row0] * ND + col], v00, v01);
                if (gr1 < n_rows)
                    red_add_v2(&g_agg[(size_t)s_tgt[row1] * ND + col], v10, v11);
            } else {
                if (gr0 < n_rows)
                    *(float2*)&out[(size_t)gr0 * ND + col] = make_float2(v00, v01);
                if (gr1 < n_rows)
                    *(float2*)&out[(size_t)gr1 * ND + col] = make_float2(v10, v11);
            }
        }
        if (MODE == 0 && wn == 0 && tg == 0) {
            if (gr0 < n_rows) atomicAdd(&g_deg[s_tgt[row0]], 1.0f);
            if (gr1 < n_rows) atomicAdd(&g_deg[s_tgt[row1]], 1.0f);
        }
    }
}

// ---------------- launch ----------------------------------------------------
extern "C" void kernel_launch(void* const* d_in, const int* in_sizes, int n_in,
                              void* d_out, int out_size) {
    // metadata order: h, e, edge_index(int32), P_w, P_b, Q_w, Q_b, W_w, W_b
    const float* h   = (const float*)d_in[0];
    const float* e   = (const float*)d_in[1];
    const int*   idx = (const int*)d_in[2];
    const float* Pw  = (const float*)d_in[3];
    const float* Pb  = (const float*)d_in[4];
    const float* Qw  = (const float*)d_in[5];
    const float* Qb  = (const float*)d_in[6];
    const float* Ww  = (const float*)d_in[7];
    const float* Wb  = (const float*)d_in[8];

    int n_nodes = in_sizes[0] / ND;
    int n_edges = in_sizes[1] / ND;
    const int* src = idx;
    const int* tgt = idx + n_edges;

    float* out_h = (float*)d_out;
    float* out_e = out_h + (size_t)n_nodes * ND;

    prep_kernel<<<256, 256>>>(Pw, Qw, Ww, n_nodes);

    int eb = (n_edges + TM - 1) / TM;
    int nb = (n_nodes + TM - 1) / TM;
    gemm_kernel<256, 0><<<eb, NTHREADS>>>(h, e, src, tgt, Pb, nullptr, n_edges);
    gemm_kernel<384, 1><<<eb, NTHREADS>>>(h, e, src, tgt, Wb, out_e, n_edges);
    gemm_kernel<256, 2><<<nb, NTHREADS>>>(h, e, src, tgt, Qb, out_h, n_nodes);
}

// round 9
// speedup vs baseline: 4.8453x; 1.2255x over previous
#include <cuda_runtime.h>
#include <cstdint>

#define ND 128
#define MAX_NODES 100000
#define MAX_EDGES 625000
#define TM 128
#define KCH 32
#define NT 128

// ---------------- device scratch (allocation-free rule) ---------------------
__device__ float g_agg[(size_t)MAX_NODES * ND];
__device__ float g_deg[MAX_NODES];
// Fragment-ordered tf32 weight images. For k-step ks, half wn, lane: 16 floats
// = b[nat 0..7][pair 0..1], n = wn*64+nat*8+(lane>>2), k = ks*8+(lane&3)+pair*4.
__device__ float g_Pfrag[(256 / 8) * 2 * 32 * 16];
__device__ float g_Qfrag[(256 / 8) * 2 * 32 * 16];
__device__ float g_Wfrag[(384 / 8) * 2 * 32 * 16];

__device__ __forceinline__ uint32_t tf32_bits(float x) {
    uint32_t r;
    asm("cvt.rna.tf32.f32 %0, %1;" : "=r"(r) : "f"(x));
    return r;
}
__device__ __forceinline__ float tf32f(float x) { return __uint_as_float(tf32_bits(x)); }

__device__ __forceinline__ uint32_t smem_u32(const void* p) {
    uint32_t a;
    asm("{ .reg .u64 t; cvta.to.shared.u64 t, %1; cvt.u32.u64 %0, t; }"
        : "=r"(a) : "l"(p));
    return a;
}
__device__ __forceinline__ void cp_async16(uint32_t dst, const void* src) {
    asm volatile("cp.async.ca.shared.global [%0], [%1], 16;"
                 :: "r"(dst), "l"(src) : "memory");
}
#define CP_COMMIT() asm volatile("cp.async.commit_group;" ::: "memory")
#define CP_WAIT0()  asm volatile("cp.async.wait_group 0;" ::: "memory")

__device__ __forceinline__ void mma_tf32(float* c, const uint32_t* a, const uint32_t* b) {
    asm volatile(
        "mma.sync.aligned.m16n8k8.row.col.f32.tf32.tf32.f32 "
        "{%0,%1,%2,%3}, {%4,%5,%6,%7}, {%8,%9}, {%0,%1,%2,%3};"
        : "+f"(c[0]), "+f"(c[1]), "+f"(c[2]), "+f"(c[3])
        : "r"(a[0]), "r"(a[1]), "r"(a[2]), "r"(a[3]), "r"(b[0]), "r"(b[1]));
}
__device__ __forceinline__ void red_add_v2(float* ptr, float v0, float v1) {
    asm volatile("red.global.add.v2.f32 [%0], {%1,%2};"
                 :: "l"(ptr), "f"(v0), "f"(v1) : "memory");
}

// ---------------- prep: zero agg/deg, build fragment-ordered weights --------
__global__ void prep_kernel(const float* __restrict__ Pw, const float* __restrict__ Qw,
                            const float* __restrict__ Ww, int n_nodes) {
    int stride = gridDim.x * blockDim.x;
    int t0 = blockIdx.x * blockDim.x + threadIdx.x;
    for (int i = t0; i < n_nodes * ND; i += stride) g_agg[i] = 0.0f;
    for (int i = t0; i < n_nodes; i += stride) g_deg[i] = 0.0f;
    for (int i = t0; i < (256 / 8) * 2 * 32 * 16; i += stride) {
        int t = i & 15, lane = (i >> 4) & 31, wn = (i >> 9) & 1, ks = i >> 10;
        int n = wn * 64 + (t >> 1) * 8 + (lane >> 2);
        int k = ks * 8 + (lane & 3) + (t & 1) * 4;
        g_Pfrag[i] = tf32f(Pw[k * ND + n]);
        g_Qfrag[i] = tf32f(Qw[k * ND + n]);
    }
    for (int i = t0; i < (384 / 8) * 2 * 32 * 16; i += stride) {
        int t = i & 15, lane = (i >> 4) & 31, wn = (i >> 9) & 1, ks = i >> 10;
        int n = wn * 64 + (t >> 1) * 8 + (lane >> 2);
        int k = ks * 8 + (lane & 3) + (t & 1) * 4;
        g_Wfrag[i] = tf32f(Ww[k * ND + n]);
    }
}

// ---------------- fused gather-GEMM-epilogue kernel -------------------------
// 4 warps, warp tile 64x64 (4 m-mats x 8 n-mats), CTA tile 128x128.
// MODE 0: msg    X=[h[src]|e]        K=256  epi: relu+bias -> red.v2 agg + deg
// MODE 1: edge   X=[e|h[src]|h[tgt]] K=384  epi: relu+bias -> out
// MODE 2: node   X=[h|agg*inv]       K=256  epi: relu+bias -> out
template <int KTOT, int MODE>
__global__ __launch_bounds__(NT, 2)
void gemm_kernel(const float* __restrict__ h, const float* __restrict__ e,
                 const int* __restrict__ src, const int* __restrict__ tgt,
                 const float* __restrict__ bias, float* __restrict__ out,
                 int n_rows) {
    // Xs stride 36: fragment-load bank = (4*row + col) % 32 -> conflict-free.
    __shared__ float Xs[2][TM][36];
    __shared__ int s_src[TM];
    __shared__ int s_tgt[TM];
    __shared__ float s_inv[TM];
    __shared__ float s_bias[ND];

    const int tid = threadIdx.x;
    const int wid = tid >> 5;
    const int lane = tid & 31;
    const int r0 = blockIdx.x * TM;

    {
        int r = r0 + tid;
        bool ok = r < n_rows;
        if (MODE == 0 || MODE == 1) {
            s_src[tid] = ok ? src[r] : 0;
            s_tgt[tid] = ok ? tgt[r] : 0;
        }
        if (MODE == 2) s_inv[tid] = ok ? (1.0f / fmaxf(g_deg[r], 1.0f)) : 0.0f;
        s_bias[tid] = bias[tid];
    }
    __syncthreads();

    const float* Wfrag = (MODE == 0) ? g_Pfrag : (MODE == 1) ? g_Wfrag : g_Qfrag;
    const uint32_t xs_base = smem_u32(Xs);

    const int wm = wid >> 1;          // 2 row-groups of 64
    const int wn = wid & 1;           // 2 col-halves of 64
    const int m_base = wm * 64;
    const int n_base = wn * 64;
    const int g = lane >> 2;
    const int tg = lane & 3;

    float c[4][8][4];
#pragma unroll
    for (int i = 0; i < 4; i++)
#pragma unroll
        for (int j = 0; j < 8; j++)
#pragma unroll
            for (int t = 0; t < 4; t++) c[i][j][t] = 0.0f;

    // ---- cp.async gather of one K-chunk into buffer b ----
    auto issue_chunk = [&](int q, int b) {
        const int kk = q * KCH;
#pragma unroll
        for (int i = tid; i < TM * 8; i += NT) {
            int r = i >> 3;          // row
            int s = i & 7;           // 16B segment
            int gr = r0 + r;
            int grc = (gr < n_rows) ? gr : 0;
            int k = kk + s * 4;
            const float* p;
            if (MODE == 0) {
                p = (k < 128) ? h + (size_t)s_src[r] * ND + k
                              : e + (size_t)grc * ND + (k - 128);
            } else if (MODE == 1) {
                if (k < 128)      p = e + (size_t)grc * ND + k;
                else if (k < 256) p = h + (size_t)s_src[r] * ND + (k - 128);
                else              p = h + (size_t)s_tgt[r] * ND + (k - 256);
            } else {
                p = (k < 128) ? h + (size_t)grc * ND + k
                              : g_agg + (size_t)grc * ND + (k - 128);
            }
            cp_async16(xs_base + (((b * TM) + r) * 36 + s * 4) * 4, p);
        }
        CP_COMMIT();
    };

    const int NCH = KTOT / KCH;
    issue_chunk(0, 0);

    for (int q = 0; q < NCH; q++) {
        const int b = q & 1;
        const int kk = q * KCH;
        CP_WAIT0();
        __syncthreads();
        if (q + 1 < NCH) issue_chunk(q + 1, (q + 1) & 1);

        // per-row scale (MODE 2, agg half only)
        float sA[8];
#pragma unroll
        for (int i = 0; i < 8; i++) sA[i] = 1.0f;
        if (MODE == 2 && kk >= 128) {
#pragma unroll
            for (int mb = 0; mb < 4; mb++) {
                sA[mb * 2]     = s_inv[m_base + mb * 16 + g];
                sA[mb * 2 + 1] = s_inv[m_base + mb * 16 + 8 + g];
            }
        }

#pragma unroll
        for (int ks = 0; ks < 4; ks++) {
            const int k0 = ks * 8;
            // A fragments: 16 conflict-free LDS
            uint32_t a[4][4];
#pragma unroll
            for (int mb = 0; mb < 4; mb++) {
                int mr = m_base + mb * 16;
                float f0 = Xs[b][mr + g][k0 + tg]         * sA[mb * 2];
                float f1 = Xs[b][mr + g + 8][k0 + tg]     * sA[mb * 2 + 1];
                float f2 = Xs[b][mr + g][k0 + tg + 4]     * sA[mb * 2];
                float f3 = Xs[b][mr + g + 8][k0 + tg + 4] * sA[mb * 2 + 1];
                a[mb][0] = tf32_bits(f0);
                a[mb][1] = tf32_bits(f1);
                a[mb][2] = tf32_bits(f2);
                a[mb][3] = tf32_bits(f3);
            }
            // B fragments: 4 coalesced float4 from fragment image (L2/L1-hot)
            const int ks_glob = q * 4 + ks;
            const float4* bp = (const float4*)(Wfrag +
                ((size_t)((ks_glob * 2 + wn) * 32 + lane)) * 16);
            float4 bf0 = __ldg(bp + 0);
            float4 bf1 = __ldg(bp + 1);
            float4 bf2 = __ldg(bp + 2);
            float4 bf3 = __ldg(bp + 3);
            uint32_t bb[8][2];
            bb[0][0] = __float_as_uint(bf0.x); bb[0][1] = __float_as_uint(bf0.y);
            bb[1][0] = __float_as_uint(bf0.z); bb[1][1] = __float_as_uint(bf0.w);
            bb[2][0] = __float_as_uint(bf1.x); bb[2][1] = __float_as_uint(bf1.y);
            bb[3][0] = __float_as_uint(bf1.z); bb[3][1] = __float_as_uint(bf1.w);
            bb[4][0] = __float_as_uint(bf2.x); bb[4][1] = __float_as_uint(bf2.y);
            bb[5][0] = __float_as_uint(bf2.z); bb[5][1] = __float_as_uint(bf2.w);
            bb[6][0] = __float_as_uint(bf3.x); bb[6][1] = __float_as_uint(bf3.y);
            bb[7][0] = __float_as_uint(bf3.z); bb[7][1] = __float_as_uint(bf3.w);
#pragma unroll
            for (int mb = 0; mb < 4; mb++)
#pragma unroll
                for (int nat = 0; nat < 8; nat++)
                    mma_tf32(c[mb][nat], a[mb], bb[nat]);
        }
        __syncthreads();
    }

    // ---- epilogue ----
#pragma unroll
    for (int mb = 0; mb < 4; mb++) {
        int row0 = m_base + mb * 16 + g;
        int row1 = row0 + 8;
        int gr0 = r0 + row0;
        int gr1 = r0 + row1;
#pragma unroll
        for (int nat = 0; nat < 8; nat++) {
            int col = n_base + nat * 8 + tg * 2;
            float b0 = s_bias[col], b1 = s_bias[col + 1];
            float v00 = fmaxf(c[mb][nat][0] + b0, 0.0f);
            float v01 = fmaxf(c[mb][nat][1] + b1, 0.0f);
            float v10 = fmaxf(c[mb][nat][2] + b0, 0.0f);
            float v11 = fmaxf(c[mb][nat][3] + b1, 0.0f);
            if (MODE == 0) {
                if (gr0 < n_rows)
                    red_add_v2(&g_agg[(size_t)s_tgt[row0] * ND + col], v00, v01);
                if (gr1 < n_rows)
                    red_add_v2(&g_agg[(size_t)s_tgt[row1] * ND + col], v10, v11);
            } else {
                if (gr0 < n_rows)
                    *(float2*)&out[(size_t)gr0 * ND + col] = make_float2(v00, v01);
                if (gr1 < n_rows)
                    *(float2*)&out[(size_t)gr1 * ND + col] = make_float2(v10, v11);
            }
        }
        if (MODE == 0 && wn == 0 && tg == 0) {
            if (gr0 < n_rows) atomicAdd(&g_deg[s_tgt[row0]], 1.0f);
            if (gr1 < n_rows) atomicAdd(&g_deg[s_tgt[row1]], 1.0f);
        }
    }
}

// ---------------- launch ----------------------------------------------------
extern "C" void kernel_launch(void* const* d_in, const int* in_sizes, int n_in,
                              void* d_out, int out_size) {
    // metadata order: h, e, edge_index(int32), P_w, P_b, Q_w, Q_b, W_w, W_b
    const float* h   = (const float*)d_in[0];
    const float* e   = (const float*)d_in[1];
    const int*   idx = (const int*)d_in[2];
    const float* Pw  = (const float*)d_in[3];
    const float* Pb  = (const float*)d_in[4];
    const float* Qw  = (const float*)d_in[5];
    const float* Qb  = (const float*)d_in[6];
    const float* Ww  = (const float*)d_in[7];
    const float* Wb  = (const float*)d_in[8];

    int n_nodes = in_sizes[0] / ND;
    int n_edges = in_sizes[1] / ND;
    const int* src = idx;
    const int* tgt = idx + n_edges;

    float* out_h = (float*)d_out;
    float* out_e = out_h + (size_t)n_nodes * ND;

    prep_kernel<<<256, 256>>>(Pw, Qw, Ww, n_nodes);

    int eb = (n_edges + TM - 1) / TM;
    int nb = (n_nodes + TM - 1) / TM;
    gemm_kernel<256, 0><<<eb, NT>>>(h, e, src, tgt, Pb, nullptr, n_edges);
    gemm_kernel<384, 1><<<eb, NT>>>(h, e, src, tgt, Wb, out_e, n_edges);
    gemm_kernel<256, 2><<<nb, NT>>>(h, e, src, tgt, Qb, out_h, n_nodes);
}

// round 14
// speedup vs baseline: 7.5328x; 1.5547x over previous
#include <cuda_runtime.h>
#include <cstdint>

#define ND 128
#define MAX_NODES 100000
#define MAX_EDGES 625000
#define TM 128
#define KCH 32
#define NT 128

// Dynamic smem layout (floats): Xs[2][TM][36] | Bs[2][4096]
#define XS_FLOATS (2 * TM * 36)
#define BS_FLOATS (2 * 4096)
#define DSM_BYTES ((XS_FLOATS + BS_FLOATS) * 4)

// ---------------- device scratch (allocation-free rule) ---------------------
__device__ float g_agg[(size_t)MAX_NODES * ND];
__device__ float g_deg[MAX_NODES];
// Fragment-ordered tf32 weight images, lane-contiguous float4 layout:
// idx = ((((ks*2 + wn)*4 + j)*32 + lane)*4 + t), nat = 2j+(t>>1), pair = t&1,
// n = wn*64 + nat*8 + (lane>>2), k = ks*8 + (lane&3) + pair*4.
// One K-chunk (4 ksteps) = 4096 floats = 16KB contiguous.
__device__ float g_Pfrag[(256 / 8) * 2 * 4 * 32 * 4];
__device__ float g_Qfrag[(256 / 8) * 2 * 4 * 32 * 4];
__device__ float g_Wfrag[(384 / 8) * 2 * 4 * 32 * 4];

__device__ __forceinline__ uint32_t tf32_bits(float x) {
    uint32_t r;
    asm("cvt.rna.tf32.f32 %0, %1;" : "=r"(r) : "f"(x));
    return r;
}
__device__ __forceinline__ float tf32f(float x) { return __uint_as_float(tf32_bits(x)); }

__device__ __forceinline__ uint32_t smem_u32(const void* p) {
    uint32_t a;
    asm("{ .reg .u64 t; cvta.to.shared.u64 t, %1; cvt.u32.u64 %0, t; }"
        : "=r"(a) : "l"(p));
    return a;
}
// .cg = bypass L1 (stream-once data; keep L1 for B/LDS)
__device__ __forceinline__ void cp_async16(uint32_t dst, const void* src) {
    asm volatile("cp.async.cg.shared.global [%0], [%1], 16;"
                 :: "r"(dst), "l"(src) : "memory");
}
#define CP_COMMIT() asm volatile("cp.async.commit_group;" ::: "memory")
#define CP_WAIT0()  asm volatile("cp.async.wait_group 0;" ::: "memory")

__device__ __forceinline__ void mma_tf32(float* c, const uint32_t* a, const uint32_t* b) {
    asm volatile(
        "mma.sync.aligned.m16n8k8.row.col.f32.tf32.tf32.f32 "
        "{%0,%1,%2,%3}, {%4,%5,%6,%7}, {%8,%9}, {%0,%1,%2,%3};"
        : "+f"(c[0]), "+f"(c[1]), "+f"(c[2]), "+f"(c[3])
        : "r"(a[0]), "r"(a[1]), "r"(a[2]), "r"(a[3]), "r"(b[0]), "r"(b[1]));
}
__device__ __forceinline__ void red_add_v2(float* ptr, float v0, float v1) {
    asm volatile("red.global.add.v2.f32 [%0], {%1,%2};"
                 :: "l"(ptr), "f"(v0), "f"(v1) : "memory");
}

// ---------------- prep: zero agg/deg, build fragment-ordered weights --------
__global__ void prep_kernel(const float* __restrict__ Pw, const float* __restrict__ Qw,
                            const float* __restrict__ Ww, int n_nodes) {
    int stride = gridDim.x * blockDim.x;
    int t0 = blockIdx.x * blockDim.x + threadIdx.x;
    for (int i = t0; i < n_nodes * ND; i += stride) g_agg[i] = 0.0f;
    for (int i = t0; i < n_nodes; i += stride) g_deg[i] = 0.0f;
    for (int i = t0; i < (256 / 8) * 2 * 4 * 32 * 4; i += stride) {
        int t = i & 3, lane = (i >> 2) & 31, j = (i >> 7) & 3, wn = (i >> 9) & 1, ks = i >> 10;
        int nat = 2 * j + (t >> 1), pair = t & 1;
        int n = wn * 64 + nat * 8 + (lane >> 2);
        int k = ks * 8 + (lane & 3) + pair * 4;
        g_Pfrag[i] = tf32f(Pw[k * ND + n]);
        g_Qfrag[i] = tf32f(Qw[k * ND + n]);
    }
    for (int i = t0; i < (384 / 8) * 2 * 4 * 32 * 4; i += stride) {
        int t = i & 3, lane = (i >> 2) & 31, j = (i >> 7) & 3, wn = (i >> 9) & 1, ks = i >> 10;
        int nat = 2 * j + (t >> 1), pair = t & 1;
        int n = wn * 64 + nat * 8 + (lane >> 2);
        int k = ks * 8 + (lane & 3) + pair * 4;
        g_Wfrag[i] = tf32f(Ww[k * ND + n]);
    }
}

// ---------------- fused gather-GEMM-epilogue kernel -------------------------
// 4 warps, warp tile 64x64, CTA tile 128x128, X+B double-buffered cp.async.
// MODE 0: msg    X=[h[src]|e]        K=256  epi: relu+bias -> red.v2 agg + deg
// MODE 1: edge   X=[e|h[src]|h[tgt]] K=384  epi: relu+bias -> out
// MODE 2: node   X=[h|agg*inv]       K=256  epi: relu+bias -> out
template <int KTOT, int MODE>
__global__ __launch_bounds__(NT, 2)
void gemm_kernel(const float* __restrict__ h, const float* __restrict__ e,
                 const int* __restrict__ src, const int* __restrict__ tgt,
                 const float* __restrict__ bias, float* __restrict__ out,
                 int n_rows) {
    extern __shared__ float dsm[];
    // Xs stride 36: fragment-load bank = (4*row + col) % 32 -> conflict-free.
    float* Xs = dsm;                     // [2][TM][36]
    float* Bs = dsm + XS_FLOATS;         // [2][4096]
    __shared__ int s_src[TM];
    __shared__ int s_tgt[TM];
    __shared__ float s_inv[TM];
    __shared__ float s_bias[ND];

    const int tid = threadIdx.x;
    const int wid = tid >> 5;
    const int lane = tid & 31;
    const int r0 = blockIdx.x * TM;

    {
        int r = r0 + tid;
        bool ok = r < n_rows;
        if (MODE == 0 || MODE == 1) {
            s_src[tid] = ok ? src[r] : 0;
            s_tgt[tid] = ok ? tgt[r] : 0;
        }
        if (MODE == 2) s_inv[tid] = ok ? (1.0f / fmaxf(g_deg[r], 1.0f)) : 0.0f;
        s_bias[tid] = bias[tid];
    }
    __syncthreads();

    const float* Wfrag = (MODE == 0) ? g_Pfrag : (MODE == 1) ? g_Wfrag : g_Qfrag;
    const uint32_t xs_base = smem_u32(Xs);
    const uint32_t bs_base = smem_u32(Bs);

    const int wm = wid >> 1;          // 2 row-groups of 64
    const int wn = wid & 1;           // 2 col-halves of 64
    const int m_base = wm * 64;
    const int n_base = wn * 64;
    const int g = lane >> 2;
    const int tg = lane & 3;

    float c[4][8][4];
#pragma unroll
    for (int i = 0; i < 4; i++)
#pragma unroll
        for (int j = 0; j < 8; j++)
#pragma unroll
            for (int t = 0; t < 4; t++) c[i][j][t] = 0.0f;

    // ---- cp.async gather of one K-chunk (X 16KB + B 16KB) into buffer b ----
    auto issue_chunk = [&](int q, int b) {
        const int kk = q * KCH;
#pragma unroll
        for (int i = tid; i < TM * 8; i += NT) {
            int r = i >> 3;          // row
            int s = i & 7;           // 16B segment
            int gr = r0 + r;
            int grc = (gr < n_rows) ? gr : 0;
            int k = kk + s * 4;
            const float* p;
            if (MODE == 0) {
                p = (k < 128) ? h + (size_t)s_src[r] * ND + k
                              : e + (size_t)grc * ND + (k - 128);
            } else if (MODE == 1) {
                if (k < 128)      p = e + (size_t)grc * ND + k;
                else if (k < 256) p = h + (size_t)s_src[r] * ND + (k - 128);
                else              p = h + (size_t)s_tgt[r] * ND + (k - 256);
            } else {
                p = (k < 128) ? h + (size_t)grc * ND + k
                              : g_agg + (size_t)grc * ND + (k - 128);
            }
            cp_async16(xs_base + (((b * TM) + r) * 36 + s * 4) * 4, p);
        }
        // B chunk: linear 16KB from fragment image (L2-hot)
        const float* bsrc = Wfrag + (size_t)q * 4096;
#pragma unroll
        for (int i = tid; i < 1024; i += NT)
            cp_async16(bs_base + (b * 4096 + i * 4) * 4, bsrc + i * 4);
        CP_COMMIT();
    };

    const int NCH = KTOT / KCH;
    issue_chunk(0, 0);

    for (int q = 0; q < NCH; q++) {
        const int b = q & 1;
        const int kk = q * KCH;
        CP_WAIT0();
        __syncthreads();
        if (q + 1 < NCH) issue_chunk(q + 1, (q + 1) & 1);

        // per-row scale (MODE 2, agg half only)
        float sA[8];
#pragma unroll
        for (int i = 0; i < 8; i++) sA[i] = 1.0f;
        if (MODE == 2 && kk >= 128) {
#pragma unroll
            for (int mb = 0; mb < 4; mb++) {
                sA[mb * 2]     = s_inv[m_base + mb * 16 + g];
                sA[mb * 2 + 1] = s_inv[m_base + mb * 16 + 8 + g];
            }
        }

        const float* Xb = Xs + b * TM * 36;
        const float* Bb = Bs + b * 4096;
#pragma unroll
        for (int ks = 0; ks < 4; ks++) {
            const int k0 = ks * 8;
            // A fragments: 16 conflict-free scalar LDS
            uint32_t a[4][4];
#pragma unroll
            for (int mb = 0; mb < 4; mb++) {
                int mr = m_base + mb * 16;
                float f0 = Xb[(mr + g) * 36 + k0 + tg]         * sA[mb * 2];
                float f1 = Xb[(mr + g + 8) * 36 + k0 + tg]     * sA[mb * 2 + 1];
                float f2 = Xb[(mr + g) * 36 + k0 + tg + 4]     * sA[mb * 2];
                float f3 = Xb[(mr + g + 8) * 36 + k0 + tg + 4] * sA[mb * 2 + 1];
                a[mb][0] = tf32_bits(f0);
                a[mb][1] = tf32_bits(f1);
                a[mb][2] = tf32_bits(f2);
                a[mb][3] = tf32_bits(f3);
            }
            // B fragments: 4 conflict-free LDS.128 from smem chunk
            const float4* bp = (const float4*)(Bb + ((ks * 2 + wn) * 4) * 128) + lane;
            float4 bf0 = bp[0];
            float4 bf1 = bp[32];
            float4 bf2 = bp[64];
            float4 bf3 = bp[96];
            uint32_t bb[8][2];
            bb[0][0] = __float_as_uint(bf0.x); bb[0][1] = __float_as_uint(bf0.y);
            bb[1][0] = __float_as_uint(bf0.z); bb[1][1] = __float_as_uint(bf0.w);
            bb[2][0] = __float_as_uint(bf1.x); bb[2][1] = __float_as_uint(bf1.y);
            bb[3][0] = __float_as_uint(bf1.z); bb[3][1] = __float_as_uint(bf1.w);
            bb[4][0] = __float_as_uint(bf2.x); bb[4][1] = __float_as_uint(bf2.y);
            bb[5][0] = __float_as_uint(bf2.z); bb[5][1] = __float_as_uint(bf2.w);
            bb[6][0] = __float_as_uint(bf3.x); bb[6][1] = __float_as_uint(bf3.y);
            bb[7][0] = __float_as_uint(bf3.z); bb[7][1] = __float_as_uint(bf3.w);
#pragma unroll
            for (int mb = 0; mb < 4; mb++)
#pragma unroll
                for (int nat = 0; nat < 8; nat++)
                    mma_tf32(c[mb][nat], a[mb], bb[nat]);
        }
        __syncthreads();
    }

    // ---- epilogue ----
#pragma unroll
    for (int mb = 0; mb < 4; mb++) {
        int row0 = m_base + mb * 16 + g;
        int row1 = row0 + 8;
        int gr0 = r0 + row0;
        int gr1 = r0 + row1;
#pragma unroll
        for (int nat = 0; nat < 8; nat++) {
            int col = n_base + nat * 8 + tg * 2;
            float b0 = s_bias[col], b1 = s_bias[col + 1];
            float v00 = fmaxf(c[mb][nat][0] + b0, 0.0f);
            float v01 = fmaxf(c[mb][nat][1] + b1, 0.0f);
            float v10 = fmaxf(c[mb][nat][2] + b0, 0.0f);
            float v11 = fmaxf(c[mb][nat][3] + b1, 0.0f);
            if (MODE == 0) {
                if (gr0 < n_rows)
                    red_add_v2(&g_agg[(size_t)s_tgt[row0] * ND + col], v00, v01);
                if (gr1 < n_rows)
                    red_add_v2(&g_agg[(size_t)s_tgt[row1] * ND + col], v10, v11);
            } else {
                if (gr0 < n_rows)
                    *(float2*)&out[(size_t)gr0 * ND + col] = make_float2(v00, v01);
                if (gr1 < n_rows)
                    *(float2*)&out[(size_t)gr1 * ND + col] = make_float2(v10, v11);
            }
        }
        if (MODE == 0 && wn == 0 && tg == 0) {
            if (gr0 < n_rows) atomicAdd(&g_deg[s_tgt[row0]], 1.0f);
            if (gr1 < n_rows) atomicAdd(&g_deg[s_tgt[row1]], 1.0f);
        }
    }
}

// ---------------- launch ----------------------------------------------------
extern "C" void kernel_launch(void* const* d_in, const int* in_sizes, int n_in,
                              void* d_out, int out_size) {
    // metadata order: h, e, edge_index(int32), P_w, P_b, Q_w, Q_b, W_w, W_b
    const float* h   = (const float*)d_in[0];
    const float* e   = (const float*)d_in[1];
    const int*   idx = (const int*)d_in[2];
    const float* Pw  = (const float*)d_in[3];
    const float* Pb  = (const float*)d_in[4];
    const float* Qw  = (const float*)d_in[5];
    const float* Qb  = (const float*)d_in[6];
    const float* Ww  = (const float*)d_in[7];
    const float* Wb  = (const float*)d_in[8];

    int n_nodes = in_sizes[0] / ND;
    int n_edges = in_sizes[1] / ND;
    const int* src = idx;
    const int* tgt = idx + n_edges;

    float* out_h = (float*)d_out;
    float* out_e = out_h + (size_t)n_nodes * ND;

    // opt-in >48KB dynamic smem (attribute set, not an allocation)
    cudaFuncSetAttribute(gemm_kernel<256, 0>,
                         cudaFuncAttributeMaxDynamicSharedMemorySize, DSM_BYTES);
    cudaFuncSetAttribute(gemm_kernel<384, 1>,
                         cudaFuncAttributeMaxDynamicSharedMemorySize, DSM_BYTES);
    cudaFuncSetAttribute(gemm_kernel<256, 2>,
                         cudaFuncAttributeMaxDynamicSharedMemorySize, DSM_BYTES);

    prep_kernel<<<256, 256>>>(Pw, Qw, Ww, n_nodes);

    int eb = (n_edges + TM - 1) / TM;
    int nb = (n_nodes + TM - 1) / TM;
    gemm_kernel<256, 0><<<eb, NT, DSM_BYTES>>>(h, e, src, tgt, Pb, nullptr, n_edges);
    gemm_kernel<384, 1><<<eb, NT, DSM_BYTES>>>(h, e, src, tgt, Wb, out_e, n_edges);
    gemm_kernel<256, 2><<<nb, NT, DSM_BYTES>>>(h, e, src, tgt, Qb, out_h, n_nodes);
}